// round 12
// baseline (speedup 1.0000x reference)
#include <cuda_runtime.h>
#include <cuda_bf16.h>
#include <cstdint>

// Problem constants (fixed by dataset)
#define BB    256      // batch
#define TT    1024     // timesteps
#define DX    64       // obs dim
#define DZ    256      // latent dim
#define DH    1024     // hidden dim
#define SS    16       // subjects
#define DF    64       // teacher-forced dims
#define ALPHA 0.2f
#define GRP   4        // batches per CTA in recurrence
#define MAXW  80       // >= sum ceil(n_s/GRP) <= (256 + 16*3)/4 = 76

typedef unsigned long long ull;

// -------- static device scratch (no allocation allowed) --------
__device__ float g_P64[DX * DF];                    // pinv(obs)[:, :64]  (64x64)
__device__ float g_forcing[(size_t)BB * TT * DF];   // 64 MB
__device__ float g_Z[(size_t)BB * TT * DZ];         // 256 MB latent trajectory
__device__ int   g_order[BB];
__device__ int4  g_work[MAXW];                      // (subject, start, cnt, 0)

// ---------------- f32x2 packed helpers (sm_10x) ----------------
__device__ __forceinline__ ull pk2(float a, float b) {
    ull r;
    asm("mov.b64 %0, {%1, %2};" : "=l"(r) : "r"(__float_as_uint(a)), "r"(__float_as_uint(b)));
    return r;
}
__device__ __forceinline__ ull dup2(float a) { return pk2(a, a); }
__device__ __forceinline__ ull fma2(ull a, ull b, ull c) {
    ull d;
    asm("fma.rn.f32x2 %0, %1, %2, %3;" : "=l"(d) : "l"(a), "l"(b), "l"(c));
    return d;
}
__device__ __forceinline__ ull add2(ull a, ull b) {
    ull d;
    asm("add.rn.f32x2 %0, %1, %2;" : "=l"(d) : "l"(a), "l"(b));
    return d;
}
__device__ __forceinline__ float2 up2(ull v) {
    unsigned lo, hi;
    asm("mov.b64 {%0, %1}, %2;" : "=r"(lo), "=r"(hi) : "l"(v));
    return make_float2(__uint_as_float(lo), __uint_as_float(hi));
}

// Cross-lane reduce of two packed accumulators.
// Result: lanes 0..15 hold total(batch01), lanes 16..31 hold total(batch23).
__device__ __forceinline__ ull wreduce(ull acc01, ull acc23, int l) {
    ull give = (l < 16) ? acc23 : acc01;
    ull got  = __shfl_xor_sync(0xffffffffu, give, 16);
    ull r    = add2((l < 16) ? acc01 : acc23, got);
    r = add2(r, __shfl_xor_sync(0xffffffffu, r, 8));
    r = add2(r, __shfl_xor_sync(0xffffffffu, r, 4));
    r = add2(r, __shfl_xor_sync(0xffffffffu, r, 2));
    r = add2(r, __shfl_xor_sync(0xffffffffu, r, 1));
    return r;
}

// ===================== Kernel A: pinv via normal equations =====================
__global__ void kpinv(const float* __restrict__ obs) {
    __shared__ float Gs[64 * 64];
    __shared__ float Au[64 * 64];
    __shared__ float fcol[64];
    __shared__ float s_piv;
    int tid = threadIdx.x;   // 256 threads

    for (int e = tid; e < 4096; e += 256) {
        int a = e >> 6, b = e & 63;
        float s = 0.f;
        for (int r = 0; r < DZ; ++r)
            s += obs[r * DX + a] * obs[r * DX + b];
        Gs[e] = s;
        Au[e] = (a == b) ? 1.f : 0.f;
    }
    __syncthreads();

    for (int c = 0; c < 64; ++c) {
        if (tid == 0) s_piv = 1.f / Gs[c * 64 + c];
        __syncthreads();
        if (tid < 128) {
            if (tid < 64) Gs[c * 64 + tid] *= s_piv;
            else          Au[c * 64 + (tid - 64)] *= s_piv;
        }
        __syncthreads();
        if (tid < 64) fcol[tid] = (tid == c) ? 0.f : Gs[tid * 64 + c];
        __syncthreads();
        for (int idx = tid; idx < 8192; idx += 256) {
            int r = idx >> 7, col = idx & 127;
            float f = fcol[r];
            if (f != 0.f) {
                if (col < 64) Gs[r * 64 + col]        -= f * Gs[c * 64 + col];
                else          Au[r * 64 + (col - 64)] -= f * Au[c * 64 + (col - 64)];
            }
        }
        __syncthreads();
    }

    for (int e = tid; e < 64 * DF; e += 256) {
        int i = e >> 6, j = e & 63;
        float s = 0.f;
        for (int k = 0; k < 64; ++k)
            s += Au[i * 64 + k] * obs[j * DX + k];
        g_P64[i * DF + j] = s;
    }
}

// ===================== Kernel B: forcing[:, :, :64] = x @ P64 =====================
// 16 rows per CTA (amortizes the 16KB P64 smem load).
__global__ void kforce(const float* __restrict__ x) {
    __shared__ float Ps[64 * 64];
    __shared__ float xs[4 * 64];
    int tid = threadIdx.x;  // 256
    for (int idx = tid; idx < 4096; idx += 256) Ps[idx] = g_P64[idx];
    int rr = tid >> 6, j = tid & 63;
    for (int it = 0; it < 4; ++it) {
        size_t r0 = (size_t)blockIdx.x * 16 + it * 4;
        __syncthreads();
        xs[tid] = x[r0 * DX + tid];
        __syncthreads();
        float acc = 0.f;
        #pragma unroll
        for (int i = 0; i < 64; ++i)
            acc += xs[rr * 64 + i] * Ps[i * 64 + j];
        g_forcing[(r0 + rr) * DF + j] = acc;
    }
}

// ===================== Kernel C: deterministic subject grouping =====================
__global__ void kgroup(const int* __restrict__ subject) {
    __shared__ int cnts[SS], base[SS];
    int tid = threadIdx.x;   // 256
    int s = subject[tid];
    if (tid < SS) {
        int c = 0;
        for (int b = 0; b < BB; ++b) c += (subject[b] == tid);
        cnts[tid] = c;
    }
    __syncthreads();
    if (tid == 0) {
        int acc = 0;
        for (int i = 0; i < SS; ++i) { base[i] = acc; acc += cnts[i]; }
    }
    __syncthreads();
    int rank = 0;
    for (int b = 0; b < tid; ++b) rank += (subject[b] == s);
    g_order[base[s] + rank] = tid;
    if (tid == 0) {
        int w = 0;
        for (int s2 = 0; s2 < SS; ++s2) {
            int n = cnts[s2];
            for (int c0 = 0; c0 < n; c0 += GRP) {
                int c = n - c0; if (c > GRP) c = GRP;
                g_work[w] = make_int4(s2, base[s2] + c0, c, 0);
                ++w;
            }
        }
        for (; w < MAXW; ++w) g_work[w] = make_int4(0, 0, 0, 0);
    }
}

// ===================== Kernel R: recurrence, GRP=4 batches/CTA, f32x2 =====================
// Native weight layouts (proven in R10/11):
//   W1: (S, dz, dh) row i contiguous over h;  W2: (S, dh, dz) row h contiguous over k.
// Phase 1: warp computes one h per pass; lanes split k via float4; two f32x2
//          accumulators carry batch-pairs (0,1) and (2,3); select-mix shfl reduce.
// Phase 2: warp computes one i per pass; lanes split h (8 float4 chunks);
//          hid cached packed in registers; same reduce; epilogue at lanes 0/16.
__global__ void __launch_bounds__(512, 1)
krecur(const float* __restrict__ A_t,  const float* __restrict__ h1_t,
       const float* __restrict__ h2_t,
       const float* __restrict__ W1_t, const float* __restrict__ W2_t) {
    __shared__ float zsc0[DZ], zsc1[DZ], zsc2[DZ], zsc3[DZ];
    __shared__ float hsc0[DH], hsc1[DH], hsc2[DH], hsc3[DH];
    __shared__ float As[DZ], h1s[DZ], h2s[DH];
    __shared__ int sb[4];

    int4 wk = g_work[blockIdx.x];
    int cnt = wk.z;
    if (cnt == 0) return;
    int s = wk.x;
    int tid = threadIdx.x;           // 512
    int w = tid >> 5, l = tid & 31;

    if (tid < 4) {
        int j = (tid < cnt) ? tid : (cnt - 1);   // pad with last valid batch
        sb[tid] = g_order[wk.y + j];
    }
    if (tid < DZ) {
        As[tid]  = A_t[s * DZ + tid];
        h1s[tid] = h1_t[s * DZ + tid];
        zsc0[tid] = 0.f; zsc1[tid] = 0.f; zsc2[tid] = 0.f; zsc3[tid] = 0.f;
    }
    for (int idx = tid; idx < DH; idx += 512) h2s[idx] = h2_t[s * DH + idx];
    __syncthreads();

    const int b0 = sb[0], b1 = sb[1], b2 = sb[2], b3 = sb[3];
    const float4* w2v = (const float4*)(W2_t + (size_t)s * DH * DZ);  // row h = 64 float4
    const float4* w1v = (const float4*)(W1_t + (size_t)s * DZ * DH);  // row i = 256 float4

    for (int t = 0; t < TT; ++t) {
        // ---- generalized teacher forcing on first DF dims ----
        // t==0: z0[:DF]=f0, then a*f0+(1-a)*f0 = f0 -> write f0 directly.
        if (tid < 256) {
            int j = tid >> 6, d = tid & 63;
            float fv = g_forcing[((size_t)sb[j] * TT + t) * DF + d];
            float* zz = (j == 0) ? zsc0 : (j == 1) ? zsc1 : (j == 2) ? zsc2 : zsc3;
            zz[d] = (t == 0) ? fv : (ALPHA * fv + (1.f - ALPHA) * zz[d]);
        }
        __syncthreads();

        // ---- pack this lane's z slice: k = l*4..l*4+3 and 128+l*4..+3 ----
        ull zp01[8], zp23[8];
        {
            float4 a0 = *(const float4*)&zsc0[l * 4];
            float4 a1 = *(const float4*)&zsc1[l * 4];
            float4 a2 = *(const float4*)&zsc2[l * 4];
            float4 a3 = *(const float4*)&zsc3[l * 4];
            zp01[0] = pk2(a0.x, a1.x); zp01[1] = pk2(a0.y, a1.y);
            zp01[2] = pk2(a0.z, a1.z); zp01[3] = pk2(a0.w, a1.w);
            zp23[0] = pk2(a2.x, a3.x); zp23[1] = pk2(a2.y, a3.y);
            zp23[2] = pk2(a2.z, a3.z); zp23[3] = pk2(a2.w, a3.w);
            float4 c0 = *(const float4*)&zsc0[128 + l * 4];
            float4 c1 = *(const float4*)&zsc1[128 + l * 4];
            float4 c2 = *(const float4*)&zsc2[128 + l * 4];
            float4 c3 = *(const float4*)&zsc3[128 + l * 4];
            zp01[4] = pk2(c0.x, c1.x); zp01[5] = pk2(c0.y, c1.y);
            zp01[6] = pk2(c0.z, c1.z); zp01[7] = pk2(c0.w, c1.w);
            zp23[4] = pk2(c2.x, c3.x); zp23[5] = pk2(c2.y, c3.y);
            zp23[6] = pk2(c2.z, c3.z); zp23[7] = pk2(c2.w, c3.w);
        }

        // ---- phase 1: hid[h] = relu( sum_k W2[h][k]*z[k] + h2[h] ), 64 passes ----
        auto p1compute = [&](int p, float4 wa, float4 wb) {
            ull acc01 = 0ull, acc23 = 0ull, ww;
            ww = dup2(wa.x); acc01 = fma2(ww, zp01[0], acc01); acc23 = fma2(ww, zp23[0], acc23);
            ww = dup2(wa.y); acc01 = fma2(ww, zp01[1], acc01); acc23 = fma2(ww, zp23[1], acc23);
            ww = dup2(wa.z); acc01 = fma2(ww, zp01[2], acc01); acc23 = fma2(ww, zp23[2], acc23);
            ww = dup2(wa.w); acc01 = fma2(ww, zp01[3], acc01); acc23 = fma2(ww, zp23[3], acc23);
            ww = dup2(wb.x); acc01 = fma2(ww, zp01[4], acc01); acc23 = fma2(ww, zp23[4], acc23);
            ww = dup2(wb.y); acc01 = fma2(ww, zp01[5], acc01); acc23 = fma2(ww, zp23[5], acc23);
            ww = dup2(wb.z); acc01 = fma2(ww, zp01[6], acc01); acc23 = fma2(ww, zp23[6], acc23);
            ww = dup2(wb.w); acc01 = fma2(ww, zp01[7], acc01); acc23 = fma2(ww, zp23[7], acc23);
            ull r = wreduce(acc01, acc23, l);
            int h = p * 16 + w;
            if (l == 0) {
                float2 v = up2(r);
                hsc0[h] = fmaxf(v.x + h2s[h], 0.f);
                hsc1[h] = fmaxf(v.y + h2s[h], 0.f);
            } else if (l == 16) {
                float2 v = up2(r);
                hsc2[h] = fmaxf(v.x + h2s[h], 0.f);
                hsc3[h] = fmaxf(v.y + h2s[h], 0.f);
            }
        };
        {
            // depth-2 software pipeline on the weight stream
            float4 c0a = w2v[(size_t)(0 * 16 + w) * 64 + l];
            float4 c0b = w2v[(size_t)(0 * 16 + w) * 64 + 32 + l];
            float4 c1a = w2v[(size_t)(1 * 16 + w) * 64 + l];
            float4 c1b = w2v[(size_t)(1 * 16 + w) * 64 + 32 + l];
            for (int p = 0; p < 64; p += 2) {
                int p2 = (p + 2 < 64) ? p + 2 : 62;   // clamped tail prefetch (unused)
                int p3 = (p + 3 < 64) ? p + 3 : 63;
                float4 n0a = w2v[(size_t)(p2 * 16 + w) * 64 + l];
                float4 n0b = w2v[(size_t)(p2 * 16 + w) * 64 + 32 + l];
                float4 n1a = w2v[(size_t)(p3 * 16 + w) * 64 + l];
                float4 n1b = w2v[(size_t)(p3 * 16 + w) * 64 + 32 + l];
                p1compute(p,     c0a, c0b);
                p1compute(p + 1, c1a, c1b);
                c0a = n0a; c0b = n0b; c1a = n1a; c1b = n1b;
            }
        }
        __syncthreads();

        // ---- cache this lane's hid slice packed: h = c*128 + l*4 + j ----
        ull hc01[32], hc23[32];
        #pragma unroll
        for (int c = 0; c < 8; ++c) {
            float4 x0 = *(const float4*)&hsc0[c * 128 + l * 4];
            float4 x1 = *(const float4*)&hsc1[c * 128 + l * 4];
            float4 x2 = *(const float4*)&hsc2[c * 128 + l * 4];
            float4 x3 = *(const float4*)&hsc3[c * 128 + l * 4];
            hc01[c * 4 + 0] = pk2(x0.x, x1.x); hc01[c * 4 + 1] = pk2(x0.y, x1.y);
            hc01[c * 4 + 2] = pk2(x0.z, x1.z); hc01[c * 4 + 3] = pk2(x0.w, x1.w);
            hc23[c * 4 + 0] = pk2(x2.x, x3.x); hc23[c * 4 + 1] = pk2(x2.y, x3.y);
            hc23[c * 4 + 2] = pk2(x2.z, x3.z); hc23[c * 4 + 3] = pk2(x2.w, x3.w);
        }

        // ---- phase 2: z[i] = A[i]*z[i] + sum_h W1[i][h]*hid[h] + h1[i], 16 passes ----
        for (int p = 0; p < 16; ++p) {
            int i = p * 16 + w;
            float4 wv[8];
            #pragma unroll
            for (int c = 0; c < 8; ++c)
                wv[c] = w1v[(size_t)i * 256 + c * 32 + l];
            ull acc01 = 0ull, acc23 = 0ull, ww;
            #pragma unroll
            for (int c = 0; c < 8; ++c) {
                ww = dup2(wv[c].x); acc01 = fma2(ww, hc01[c * 4 + 0], acc01); acc23 = fma2(ww, hc23[c * 4 + 0], acc23);
                ww = dup2(wv[c].y); acc01 = fma2(ww, hc01[c * 4 + 1], acc01); acc23 = fma2(ww, hc23[c * 4 + 1], acc23);
                ww = dup2(wv[c].z); acc01 = fma2(ww, hc01[c * 4 + 2], acc01); acc23 = fma2(ww, hc23[c * 4 + 2], acc23);
                ww = dup2(wv[c].w); acc01 = fma2(ww, hc01[c * 4 + 3], acc01); acc23 = fma2(ww, hc23[c * 4 + 3], acc23);
            }
            ull r = wreduce(acc01, acc23, l);
            if (l == 0) {
                float2 v = up2(r);
                float zn0 = fmaf(As[i], zsc0[i], v.x + h1s[i]);
                float zn1 = fmaf(As[i], zsc1[i], v.y + h1s[i]);
                zsc0[i] = zn0; zsc1[i] = zn1;
                g_Z[((size_t)b0 * TT + t) * DZ + i] = zn0;
                if (cnt > 1) g_Z[((size_t)b1 * TT + t) * DZ + i] = zn1;
            } else if (l == 16) {
                float2 v = up2(r);
                float zn2 = fmaf(As[i], zsc2[i], v.x + h1s[i]);
                float zn3 = fmaf(As[i], zsc3[i], v.y + h1s[i]);
                zsc2[i] = zn2; zsc3[i] = zn3;
                if (cnt > 2) g_Z[((size_t)b2 * TT + t) * DZ + i] = zn2;
                if (cnt > 3) g_Z[((size_t)b3 * TT + t) * DZ + i] = zn3;
            }
        }
        __syncthreads();
    }
}

// ===================== Kernel D: decode out = Z @ obs =====================
// 128 rows per CTA (amortizes the 64KB obs smem load).
__global__ void kdecode(const float* __restrict__ obs, float* __restrict__ out) {
    extern __shared__ float smd[];
    float* obss = smd;               // DZ*64 = 16384 floats (64 KB)
    float* zsm  = obss + DZ * 64;    // 32*DZ =  8192 floats (32 KB)
    int tid = threadIdx.x;           // 512
    for (int idx = tid; idx < DZ * 64; idx += 512) obss[idx] = obs[idx];
    int g = tid & 15, j = tid >> 4;  // 16 x-groups of 4, 32 rows
    int x0 = g * 4;
    for (int it = 0; it < 4; ++it) {
        size_t r0 = (size_t)blockIdx.x * 128 + it * 32;
        __syncthreads();
        for (int idx = tid; idx < 32 * DZ; idx += 512) zsm[idx] = g_Z[r0 * DZ + idx];
        __syncthreads();
        float4 acc = {0, 0, 0, 0};
        const float* zp = zsm + j * DZ;
        #pragma unroll 4
        for (int zi = 0; zi < DZ; ++zi) {
            float zv = zp[zi];
            float4 ov = *(const float4*)&obss[zi * 64 + x0];
            acc.x += zv * ov.x; acc.y += zv * ov.y; acc.z += zv * ov.z; acc.w += zv * ov.w;
        }
        *(float4*)&out[(r0 + j) * 64 + x0] = acc;
    }
}

// ===================== host =====================
extern "C" void kernel_launch(void* const* d_in, const int* in_sizes, int n_in,
                              void* d_out, int out_size) {
    const float* x_gt  = (const float*)d_in[0];   // (256,1024,64)
    const int*   subj  = (const int*)  d_in[1];   // (256,)
    const float* obs   = (const float*)d_in[2];   // (256,64)
    const float* A_t   = (const float*)d_in[3];   // (16,256)
    const float* W1_t  = (const float*)d_in[4];   // (16,256,1024)
    const float* W2_t  = (const float*)d_in[5];   // (16,1024,256)
    const float* h1_t  = (const float*)d_in[6];   // (16,256)
    const float* h2_t  = (const float*)d_in[7];   // (16,1024)
    float* out = (float*)d_out;

    cudaFuncSetAttribute(kdecode, cudaFuncAttributeMaxDynamicSharedMemorySize, 98304);

    kpinv<<<1, 256>>>(obs);
    kforce<<<(BB * TT) / 16, 256>>>(x_gt);
    kgroup<<<1, 256>>>(subj);
    krecur<<<MAXW, 512>>>(A_t, h1_t, h2_t, W1_t, W2_t);
    kdecode<<<(BB * TT) / 128, 512, 98304>>>(obs, out);
}

// round 13
// speedup vs baseline: 1.2578x; 1.2578x over previous
#include <cuda_runtime.h>
#include <cuda_bf16.h>
#include <cstdint>

// Problem constants (fixed by dataset)
#define BB    256      // batch
#define TT    1024     // timesteps
#define DX    64       // obs dim
#define DZ    256      // latent dim
#define DH    1024     // hidden dim
#define SS    16       // subjects
#define DF    64       // teacher-forced dims
#define ALPHA 0.2f
#define GRP   3        // batches per CTA in recurrence
#define MAXW  104      // >= floor(256/3) + 16 = 101

// -------- static device scratch (no allocation allowed) --------
__device__ float g_P64[DX * DF];                    // pinv(obs)[:, :64]  (64x64)
__device__ float g_forcing[(size_t)BB * TT * DF];   // 64 MB
__device__ float g_Z[(size_t)BB * TT * DZ];         // 256 MB latent trajectory
__device__ int   g_order[BB];
__device__ int4  g_work[MAXW];                      // (subject, start, cnt, 0)

__device__ __forceinline__ float dot4(float4 a, float4 b) {
    return fmaf(a.x, b.x, fmaf(a.y, b.y, fmaf(a.z, b.z, a.w * b.w)));
}

// ===================== Kernel A: pinv via normal equations =====================
__global__ void kpinv(const float* __restrict__ obs) {
    __shared__ float Gs[64 * 64];
    __shared__ float Au[64 * 64];
    __shared__ float fcol[64];
    __shared__ float s_piv;
    int tid = threadIdx.x;   // 256 threads

    for (int e = tid; e < 4096; e += 256) {
        int a = e >> 6, b = e & 63;
        float s = 0.f;
        for (int r = 0; r < DZ; ++r)
            s += obs[r * DX + a] * obs[r * DX + b];
        Gs[e] = s;
        Au[e] = (a == b) ? 1.f : 0.f;
    }
    __syncthreads();

    for (int c = 0; c < 64; ++c) {
        if (tid == 0) s_piv = 1.f / Gs[c * 64 + c];
        __syncthreads();
        if (tid < 128) {
            if (tid < 64) Gs[c * 64 + tid] *= s_piv;
            else          Au[c * 64 + (tid - 64)] *= s_piv;
        }
        __syncthreads();
        if (tid < 64) fcol[tid] = (tid == c) ? 0.f : Gs[tid * 64 + c];
        __syncthreads();
        for (int idx = tid; idx < 8192; idx += 256) {
            int r = idx >> 7, col = idx & 127;
            float f = fcol[r];
            if (f != 0.f) {
                if (col < 64) Gs[r * 64 + col]        -= f * Gs[c * 64 + col];
                else          Au[r * 64 + (col - 64)] -= f * Au[c * 64 + (col - 64)];
            }
        }
        __syncthreads();
    }

    for (int e = tid; e < 64 * DF; e += 256) {
        int i = e >> 6, j = e & 63;
        float s = 0.f;
        for (int k = 0; k < 64; ++k)
            s += Au[i * 64 + k] * obs[j * DX + k];
        g_P64[i * DF + j] = s;
    }
}

// ===================== Kernel B: forcing[:, :, :64] = x @ P64 =====================
__global__ void kforce(const float* __restrict__ x) {
    __shared__ float Ps[64 * 64];
    __shared__ float xs[4 * 64];
    int tid = threadIdx.x;  // 256
    for (int idx = tid; idx < 4096; idx += 256) Ps[idx] = g_P64[idx];
    int rr = tid >> 6, j = tid & 63;
    for (int it = 0; it < 4; ++it) {
        size_t r0 = (size_t)blockIdx.x * 16 + it * 4;
        __syncthreads();
        xs[tid] = x[r0 * DX + tid];
        __syncthreads();
        float acc = 0.f;
        #pragma unroll
        for (int i = 0; i < 64; ++i)
            acc += xs[rr * 64 + i] * Ps[i * 64 + j];
        g_forcing[(r0 + rr) * DF + j] = acc;
    }
}

// ===================== Kernel C: deterministic subject grouping =====================
__global__ void kgroup(const int* __restrict__ subject) {
    __shared__ int cnts[SS], base[SS];
    int tid = threadIdx.x;   // 256
    int s = subject[tid];
    if (tid < SS) {
        int c = 0;
        for (int b = 0; b < BB; ++b) c += (subject[b] == tid);
        cnts[tid] = c;
    }
    __syncthreads();
    if (tid == 0) {
        int acc = 0;
        for (int i = 0; i < SS; ++i) { base[i] = acc; acc += cnts[i]; }
    }
    __syncthreads();
    int rank = 0;
    for (int b = 0; b < tid; ++b) rank += (subject[b] == s);
    g_order[base[s] + rank] = tid;
    if (tid == 0) {
        int w = 0;
        for (int s2 = 0; s2 < SS; ++s2) {
            int n = cnts[s2];
            for (int c0 = 0; c0 < n; c0 += GRP) {
                int c = n - c0; if (c > GRP) c = GRP;
                g_work[w] = make_int4(s2, base[s2] + c0, c, 0);
                ++w;
            }
        }
        for (; w < MAXW; ++w) g_work[w] = make_int4(0, 0, 0, 0);
    }
}

// ===================== Kernel R: recurrence, GRP=3 batches/CTA =====================
// Native weight layouts (proven in R11/R12):
//   W1: (S, dz, dh) row i contiguous over h;  W2: (S, dh, dz) row h contiguous over k.
// 1024 threads = 32 warps. Warp-per-output-row with float4 coalesced weight loads.
// 3 scalar accumulators (one per batch). Reduce: batches 0/1 share one 5-shfl
// pair-reduce (results land on lanes 0 and 16); batch 2 uses a butterfly (valid
// on all lanes). 10 scalar shfl per pass total.
__global__ void __launch_bounds__(1024, 1)
krecur(const float* __restrict__ A_t,  const float* __restrict__ h1_t,
       const float* __restrict__ h2_t,
       const float* __restrict__ W1_t, const float* __restrict__ W2_t) {
    __shared__ float zs[GRP][DZ];
    __shared__ float hid[GRP][DH];
    __shared__ float As[DZ], h1s[DZ], h2s[DH];
    __shared__ int sb[GRP];

    int4 wk = g_work[blockIdx.x];
    int cnt = wk.z;
    if (cnt == 0) return;
    int s = wk.x;
    int tid = threadIdx.x;           // 1024
    int w = tid >> 5, l = tid & 31;

    if (tid < GRP) sb[tid] = g_order[wk.y + ((tid < cnt) ? tid : cnt - 1)];
    if (tid < DZ) {
        As[tid]  = A_t[s * DZ + tid];
        h1s[tid] = h1_t[s * DZ + tid];
        zs[0][tid] = 0.f; zs[1][tid] = 0.f; zs[2][tid] = 0.f;
    }
    h2s[tid] = h2_t[s * DH + tid];
    __syncthreads();

    const int b0 = sb[0], b1 = sb[1], b2 = sb[2];
    const float4* w2v = (const float4*)(W2_t + (size_t)s * DH * DZ);  // row h = 64 float4
    const float4* w1v = (const float4*)(W1_t + (size_t)s * DZ * DH);  // row i = 256 float4

    for (int t = 0; t < TT; ++t) {
        // ---- generalized teacher forcing on first DF dims ----
        // t==0: z0[:DF]=f0, then a*f0+(1-a)*f0 = f0 -> write f0 directly.
        if (tid < GRP * DF) {
            int j = tid >> 6, d = tid & 63;
            float fv = g_forcing[((size_t)sb[j] * TT + t) * DF + d];
            zs[j][d] = (t == 0) ? fv : (ALPHA * fv + (1.f - ALPHA) * zs[j][d]);
        }
        __syncthreads();

        // cache this lane's z slice (reused for all 32 phase-1 passes)
        float4 z0a = *(const float4*)&zs[0][4 * l];
        float4 z0b = *(const float4*)&zs[0][128 + 4 * l];
        float4 z1a = *(const float4*)&zs[1][4 * l];
        float4 z1b = *(const float4*)&zs[1][128 + 4 * l];
        float4 z2a = *(const float4*)&zs[2][4 * l];
        float4 z2b = *(const float4*)&zs[2][128 + 4 * l];

        // ---- phase 1: hid[b][h] = relu( sum_k W2[h][k]*z[b][k] + h2[h] ) ----
        #pragma unroll 2
        for (int p = 0; p < 32; ++p) {
            int h = p * 32 + w;
            const float4* row = w2v + (size_t)h * 64;
            float4 wa = row[l], wb = row[32 + l];
            float a0 = dot4(wa, z0a) + dot4(wb, z0b);
            float a1 = dot4(wa, z1a) + dot4(wb, z1b);
            float a2 = dot4(wa, z2a) + dot4(wb, z2b);
            // pair reduce (a0,a1): lanes 0..15 accumulate batch0, 16..31 batch1
            float give = (l & 16) ? a0 : a1;
            float got  = __shfl_xor_sync(0xffffffffu, give, 16);
            float r01  = ((l & 16) ? a1 : a0) + got;
            float r2   = a2 + __shfl_xor_sync(0xffffffffu, a2, 16);
            #pragma unroll
            for (int d = 8; d >= 1; d >>= 1) {
                r01 += __shfl_xor_sync(0xffffffffu, r01, d);
                r2  += __shfl_xor_sync(0xffffffffu, r2, d);
            }
            if (l == 0) {
                hid[0][h] = fmaxf(r01 + h2s[h], 0.f);
                hid[2][h] = fmaxf(r2  + h2s[h], 0.f);
            } else if (l == 16) {
                hid[1][h] = fmaxf(r01 + h2s[h], 0.f);
            }
        }
        __syncthreads();

        // ---- phase 2: z[b][i] = A[i]*z[b][i] + sum_h W1[i][h]*hid[b][h] + h1[i] ----
        #pragma unroll 2
        for (int p = 0; p < 8; ++p) {
            int i = p * 32 + w;
            const float4* row = w1v + (size_t)i * 256;
            float a0 = 0.f, a1 = 0.f, a2 = 0.f;
            #pragma unroll
            for (int c = 0; c < 8; ++c) {
                float4 wv = row[c * 32 + l];
                float4 h0 = *(const float4*)&hid[0][c * 128 + 4 * l];
                float4 h1v = *(const float4*)&hid[1][c * 128 + 4 * l];
                float4 h2v = *(const float4*)&hid[2][c * 128 + 4 * l];
                a0 += dot4(wv, h0);
                a1 += dot4(wv, h1v);
                a2 += dot4(wv, h2v);
            }
            float give = (l & 16) ? a0 : a1;
            float got  = __shfl_xor_sync(0xffffffffu, give, 16);
            float r01  = ((l & 16) ? a1 : a0) + got;
            float r2   = a2 + __shfl_xor_sync(0xffffffffu, a2, 16);
            #pragma unroll
            for (int d = 8; d >= 1; d >>= 1) {
                r01 += __shfl_xor_sync(0xffffffffu, r01, d);
                r2  += __shfl_xor_sync(0xffffffffu, r2, d);
            }
            if (l == 0) {
                float zn0 = fmaf(As[i], zs[0][i], r01 + h1s[i]);
                float zn2 = fmaf(As[i], zs[2][i], r2  + h1s[i]);
                zs[0][i] = zn0;
                zs[2][i] = zn2;
                g_Z[((size_t)b0 * TT + t) * DZ + i] = zn0;
                if (cnt > 2) g_Z[((size_t)b2 * TT + t) * DZ + i] = zn2;
            } else if (l == 16) {
                float zn1 = fmaf(As[i], zs[1][i], r01 + h1s[i]);
                zs[1][i] = zn1;
                if (cnt > 1) g_Z[((size_t)b1 * TT + t) * DZ + i] = zn1;
            }
        }
        __syncthreads();
    }
}

// ===================== Kernel D: decode out = Z @ obs =====================
__global__ void kdecode(const float* __restrict__ obs, float* __restrict__ out) {
    extern __shared__ float smd[];
    float* obss = smd;               // DZ*64 = 16384 floats (64 KB)
    float* zsm  = obss + DZ * 64;    // 32*DZ =  8192 floats (32 KB)
    int tid = threadIdx.x;           // 512
    for (int idx = tid; idx < DZ * 64; idx += 512) obss[idx] = obs[idx];
    int g = tid & 15, j = tid >> 4;  // 16 x-groups of 4, 32 rows
    int x0 = g * 4;
    for (int it = 0; it < 4; ++it) {
        size_t r0 = (size_t)blockIdx.x * 128 + it * 32;
        __syncthreads();
        for (int idx = tid; idx < 32 * DZ; idx += 512) zsm[idx] = g_Z[r0 * DZ + idx];
        __syncthreads();
        float4 acc = {0, 0, 0, 0};
        const float* zp = zsm + j * DZ;
        #pragma unroll 4
        for (int zi = 0; zi < DZ; ++zi) {
            float zv = zp[zi];
            float4 ov = *(const float4*)&obss[zi * 64 + x0];
            acc.x += zv * ov.x; acc.y += zv * ov.y; acc.z += zv * ov.z; acc.w += zv * ov.w;
        }
        *(float4*)&out[(r0 + j) * 64 + x0] = acc;
    }
}

// ===================== host =====================
extern "C" void kernel_launch(void* const* d_in, const int* in_sizes, int n_in,
                              void* d_out, int out_size) {
    const float* x_gt  = (const float*)d_in[0];   // (256,1024,64)
    const int*   subj  = (const int*)  d_in[1];   // (256,)
    const float* obs   = (const float*)d_in[2];   // (256,64)
    const float* A_t   = (const float*)d_in[3];   // (16,256)
    const float* W1_t  = (const float*)d_in[4];   // (16,256,1024)
    const float* W2_t  = (const float*)d_in[5];   // (16,1024,256)
    const float* h1_t  = (const float*)d_in[6];   // (16,256)
    const float* h2_t  = (const float*)d_in[7];   // (16,1024)
    float* out = (float*)d_out;

    cudaFuncSetAttribute(kdecode, cudaFuncAttributeMaxDynamicSharedMemorySize, 98304);

    kpinv<<<1, 256>>>(obs);
    kforce<<<(BB * TT) / 16, 256>>>(x_gt);
    kgroup<<<1, 256>>>(subj);
    krecur<<<MAXW, 1024>>>(A_t, h1_t, h2_t, W1_t, W2_t);
    kdecode<<<(BB * TT) / 128, 512, 98304>>>(obs, out);
}

// round 14
// speedup vs baseline: 2.6463x; 2.1040x over previous
#include <cuda_runtime.h>
#include <cuda_bf16.h>
#include <cstdint>

// Problem constants (fixed by dataset)
#define BB    256      // batch
#define TT    1024     // timesteps
#define DX    64       // obs dim
#define DZ    256      // latent dim
#define DH    1024     // hidden dim
#define SS    16       // subjects
#define DF    64       // teacher-forced dims
#define ALPHA 0.2f
#define GRP   4        // batches per work item
#define NIT   76       // max work items: sum ceil(n_s/4) <= (256+3*16)/4 = 76

// -------- static device scratch (no allocation allowed) --------
__device__ float g_P64[DX * DF];                    // pinv(obs)[:, :64]  (64x64)
__device__ float g_forcing[(size_t)BB * TT * DF];   // 64 MB
__device__ float g_Z[(size_t)BB * TT * DZ];         // 256 MB latent trajectory
__device__ int   g_order[BB];
__device__ int4  g_work[NIT];                       // (subject, start, cnt, 0)

__device__ __forceinline__ float dot4(float4 a, float4 b) {
    return fmaf(a.x, b.x, fmaf(a.y, b.y, fmaf(a.z, b.z, a.w * b.w)));
}
__device__ __forceinline__ uint32_t smem_u32(const void* p) {
    uint32_t a;
    asm("{ .reg .u64 t; cvta.to.shared.u64 t, %1; cvt.u32.u64 %0, t; }" : "=r"(a) : "l"(p));
    return a;
}
__device__ __forceinline__ uint32_t mapa_u32(uint32_t a, uint32_t r) {
    uint32_t d;
    asm("mapa.shared::cluster.u32 %0, %1, %2;" : "=r"(d) : "r"(a), "r"(r));
    return d;
}
__device__ __forceinline__ void st_cluster(uint32_t a, float v) {
    asm volatile("st.shared::cluster.f32 [%0], %1;" :: "r"(a), "f"(v) : "memory");
}
#define CLUSTER_SYNC_() do { \
    asm volatile("barrier.cluster.arrive.aligned;" ::: "memory"); \
    asm volatile("barrier.cluster.wait.aligned;"   ::: "memory"); \
} while (0)

// ===================== Kernel A: pinv via normal equations =====================
__global__ void kpinv(const float* __restrict__ obs) {
    __shared__ float Gs[64 * 64];
    __shared__ float Au[64 * 64];
    __shared__ float fcol[64];
    __shared__ float s_piv;
    int tid = threadIdx.x;   // 256 threads

    for (int e = tid; e < 4096; e += 256) {
        int a = e >> 6, b = e & 63;
        float s = 0.f;
        for (int r = 0; r < DZ; ++r)
            s += obs[r * DX + a] * obs[r * DX + b];
        Gs[e] = s;
        Au[e] = (a == b) ? 1.f : 0.f;
    }
    __syncthreads();

    for (int c = 0; c < 64; ++c) {
        if (tid == 0) s_piv = 1.f / Gs[c * 64 + c];
        __syncthreads();
        if (tid < 128) {
            if (tid < 64) Gs[c * 64 + tid] *= s_piv;
            else          Au[c * 64 + (tid - 64)] *= s_piv;
        }
        __syncthreads();
        if (tid < 64) fcol[tid] = (tid == c) ? 0.f : Gs[tid * 64 + c];
        __syncthreads();
        for (int idx = tid; idx < 8192; idx += 256) {
            int r = idx >> 7, col = idx & 127;
            float f = fcol[r];
            if (f != 0.f) {
                if (col < 64) Gs[r * 64 + col]        -= f * Gs[c * 64 + col];
                else          Au[r * 64 + (col - 64)] -= f * Au[c * 64 + (col - 64)];
            }
        }
        __syncthreads();
    }

    for (int e = tid; e < 64 * DF; e += 256) {
        int i = e >> 6, j = e & 63;
        float s = 0.f;
        for (int k = 0; k < 64; ++k)
            s += Au[i * 64 + k] * obs[j * DX + k];
        g_P64[i * DF + j] = s;
    }
}

// ===================== Kernel B: forcing[:, :, :64] = x @ P64 =====================
__global__ void kforce(const float* __restrict__ x) {
    __shared__ float Ps[64 * 64];
    __shared__ float xs[4 * 64];
    int tid = threadIdx.x;  // 256
    for (int idx = tid; idx < 4096; idx += 256) Ps[idx] = g_P64[idx];
    int rr = tid >> 6, j = tid & 63;
    for (int it = 0; it < 4; ++it) {
        size_t r0 = (size_t)blockIdx.x * 16 + it * 4;
        __syncthreads();
        xs[tid] = x[r0 * DX + tid];
        __syncthreads();
        float acc = 0.f;
        #pragma unroll
        for (int i = 0; i < 64; ++i)
            acc += xs[rr * 64 + i] * Ps[i * 64 + j];
        g_forcing[(r0 + rr) * DF + j] = acc;
    }
}

// ===================== Kernel C: deterministic subject grouping (GRP=4) =====================
__global__ void kgroup(const int* __restrict__ subject) {
    __shared__ int cnts[SS], base[SS];
    int tid = threadIdx.x;   // 256
    int s = subject[tid];
    if (tid < SS) {
        int c = 0;
        for (int b = 0; b < BB; ++b) c += (subject[b] == tid);
        cnts[tid] = c;
    }
    __syncthreads();
    if (tid == 0) {
        int acc = 0;
        for (int i = 0; i < SS; ++i) { base[i] = acc; acc += cnts[i]; }
    }
    __syncthreads();
    int rank = 0;
    for (int b = 0; b < tid; ++b) rank += (subject[b] == s);
    g_order[base[s] + rank] = tid;
    if (tid == 0) {
        int w = 0;
        for (int s2 = 0; s2 < SS; ++s2) {
            int n = cnts[s2];
            for (int c0 = 0; c0 < n; c0 += GRP) {
                int c = n - c0; if (c > GRP) c = GRP;
                g_work[w] = make_int4(s2, base[s2] + c0, c, 0);
                ++w;
            }
        }
        for (; w < NIT; ++w) g_work[w] = make_int4(0, 0, 0, 0);
    }
}

// ===================== Kernel R: recurrence, cluster-2, GRP=4 =====================
// Each work item (subject, <=4 batches) is handled by a 2-CTA cluster.
// Rank r owns h in [512r, 512r+512) for phase 1 and i in [128r, 128r+128) for
// phase 2. Halves exchanged via DSMEM stores; 2 cluster barriers per step.
// Phase 2 computes 4 output rows per warp from ONE hid load (L1-port relief).
__global__ void __launch_bounds__(1024, 1) __cluster_dims__(2, 1, 1)
krecur(const float* __restrict__ A_t,  const float* __restrict__ h1_t,
       const float* __restrict__ h2_t,
       const float* __restrict__ W1_t, const float* __restrict__ W2_t) {
    __shared__ float zs[GRP][DZ];
    __shared__ float hid[GRP][DH];
    __shared__ float As[DZ], h1s[DZ], h2s[DH];
    __shared__ int sb[GRP];

    int item = blockIdx.x >> 1;
    uint32_t rank;
    asm("mov.u32 %0, %%cluster_ctarank;" : "=r"(rank));

    int4 wk = g_work[item];
    int cnt = wk.z;
    if (cnt == 0) return;                 // both CTAs of the cluster exit together
    int s = wk.x;
    int tid = threadIdx.x;                // 1024
    int w = tid >> 5, l = tid & 31;

    if (tid < GRP) sb[tid] = g_order[wk.y + ((tid < cnt) ? tid : cnt - 1)];
    if (tid < DZ) {
        As[tid]  = A_t[s * DZ + tid];
        h1s[tid] = h1_t[s * DZ + tid];
        zs[0][tid] = 0.f; zs[1][tid] = 0.f; zs[2][tid] = 0.f; zs[3][tid] = 0.f;
    }
    h2s[tid] = h2_t[s * DH + tid];
    __syncthreads();

    const int b0 = sb[0], b1 = sb[1], b2 = sb[2], b3 = sb[3];
    const float4* w2v = (const float4*)(W2_t + (size_t)s * DH * DZ);  // row h = 64 float4
    const float4* w1v = (const float4*)(W1_t + (size_t)s * DZ * DH);  // row i = 256 float4

    const uint32_t peer  = rank ^ 1u;
    const uint32_t hid_r = mapa_u32(smem_u32(hid), peer);
    const uint32_t zs_r  = mapa_u32(smem_u32(zs),  peer);

    const int hbase = (int)rank * 512;    // phase-1 h range
    const int ibase = (int)rank * 128;    // phase-2 i range

    for (int t = 0; t < TT; ++t) {
        // ---- generalized teacher forcing on first DF dims (both CTAs, identical) ----
        // t==0: z0[:DF]=f0, then a*f0+(1-a)*f0 = f0 -> write f0 directly.
        if (tid < GRP * DF) {
            int j = tid >> 6, d = tid & 63;
            float fv = g_forcing[((size_t)sb[j] * TT + t) * DF + d];
            zs[j][d] = (t == 0) ? fv : (ALPHA * fv + (1.f - ALPHA) * zs[j][d]);
        }
        __syncthreads();

        // cache z for batches 0..2 in regs; batch 3 via LDS inside the pass
        float4 z0a = *(const float4*)&zs[0][4 * l];
        float4 z0b = *(const float4*)&zs[0][128 + 4 * l];
        float4 z1a = *(const float4*)&zs[1][4 * l];
        float4 z1b = *(const float4*)&zs[1][128 + 4 * l];
        float4 z2a = *(const float4*)&zs[2][4 * l];
        float4 z2b = *(const float4*)&zs[2][128 + 4 * l];

        // ---- phase 1: hid[b][h] = relu( sum_k W2[h][k]*z[b][k] + h2[h] ), own 512 rows ----
        #pragma unroll 2
        for (int p = 0; p < 16; ++p) {
            int h = hbase + p * 32 + w;
            const float4* row = w2v + (size_t)h * 64;
            float4 wa = row[l], wb = row[32 + l];
            float4 z3a = *(const float4*)&zs[3][4 * l];
            float4 z3b = *(const float4*)&zs[3][128 + 4 * l];
            float a0 = dot4(wa, z0a) + dot4(wb, z0b);
            float a1 = dot4(wa, z1a) + dot4(wb, z1b);
            float a2 = dot4(wa, z2a) + dot4(wb, z2b);
            float a3 = dot4(wa, z3a) + dot4(wb, z3b);
            // pair reduces: (a0,a1) and (a2,a3); lanes 0 -> (b0,b2), 16 -> (b1,b3)
            float r01 = ((l & 16) ? a1 : a0) + __shfl_xor_sync(0xffffffffu, (l & 16) ? a0 : a1, 16);
            float r23 = ((l & 16) ? a3 : a2) + __shfl_xor_sync(0xffffffffu, (l & 16) ? a2 : a3, 16);
            #pragma unroll
            for (int d = 8; d >= 1; d >>= 1) {
                r01 += __shfl_xor_sync(0xffffffffu, r01, d);
                r23 += __shfl_xor_sync(0xffffffffu, r23, d);
            }
            if (l == 0) {
                float v0 = fmaxf(r01 + h2s[h], 0.f);
                float v2 = fmaxf(r23 + h2s[h], 0.f);
                hid[0][h] = v0; hid[2][h] = v2;
                st_cluster(hid_r + (uint32_t)(0 * DH + h) * 4u, v0);
                st_cluster(hid_r + (uint32_t)(2 * DH + h) * 4u, v2);
            } else if (l == 16) {
                float v1 = fmaxf(r01 + h2s[h], 0.f);
                float v3 = fmaxf(r23 + h2s[h], 0.f);
                hid[1][h] = v1; hid[3][h] = v3;
                st_cluster(hid_r + (uint32_t)(1 * DH + h) * 4u, v1);
                st_cluster(hid_r + (uint32_t)(3 * DH + h) * 4u, v3);
            }
        }
        // barrier A: full hid assembled in both CTAs
        CLUSTER_SYNC_();

        // ---- phase 2: z[b][i] = A[i]*z[b][i] + sum_h W1[i][h]*hid[b][h] + h1[i] ----
        // warp w covers rows i = ibase + w + 32q, q=0..3; hid chunks loaded ONCE per c.
        {
            float acc[4][4];
            #pragma unroll
            for (int q = 0; q < 4; ++q)
                #pragma unroll
                for (int b = 0; b < 4; ++b) acc[q][b] = 0.f;
            #pragma unroll
            for (int c = 0; c < 8; ++c) {
                float4 hc0 = *(const float4*)&hid[0][c * 128 + 4 * l];
                float4 hc1 = *(const float4*)&hid[1][c * 128 + 4 * l];
                float4 hc2 = *(const float4*)&hid[2][c * 128 + 4 * l];
                float4 hc3 = *(const float4*)&hid[3][c * 128 + 4 * l];
                #pragma unroll
                for (int q = 0; q < 4; ++q) {
                    int i = ibase + w + 32 * q;
                    float4 wv = w1v[(size_t)i * 256 + c * 32 + l];
                    acc[q][0] += dot4(wv, hc0);
                    acc[q][1] += dot4(wv, hc1);
                    acc[q][2] += dot4(wv, hc2);
                    acc[q][3] += dot4(wv, hc3);
                }
            }
            #pragma unroll
            for (int q = 0; q < 4; ++q) {
                int i = ibase + w + 32 * q;
                float a0 = acc[q][0], a1 = acc[q][1], a2 = acc[q][2], a3 = acc[q][3];
                float r01 = ((l & 16) ? a1 : a0) + __shfl_xor_sync(0xffffffffu, (l & 16) ? a0 : a1, 16);
                float r23 = ((l & 16) ? a3 : a2) + __shfl_xor_sync(0xffffffffu, (l & 16) ? a2 : a3, 16);
                #pragma unroll
                for (int d = 8; d >= 1; d >>= 1) {
                    r01 += __shfl_xor_sync(0xffffffffu, r01, d);
                    r23 += __shfl_xor_sync(0xffffffffu, r23, d);
                }
                if (l == 0) {
                    float zn0 = fmaf(As[i], zs[0][i], r01 + h1s[i]);
                    float zn2 = fmaf(As[i], zs[2][i], r23 + h1s[i]);
                    zs[0][i] = zn0; zs[2][i] = zn2;
                    st_cluster(zs_r + (uint32_t)(0 * DZ + i) * 4u, zn0);
                    st_cluster(zs_r + (uint32_t)(2 * DZ + i) * 4u, zn2);
                    g_Z[((size_t)b0 * TT + t) * DZ + i] = zn0;
                    if (cnt > 2) g_Z[((size_t)b2 * TT + t) * DZ + i] = zn2;
                } else if (l == 16) {
                    float zn1 = fmaf(As[i], zs[1][i], r01 + h1s[i]);
                    float zn3 = fmaf(As[i], zs[3][i], r23 + h1s[i]);
                    zs[1][i] = zn1; zs[3][i] = zn3;
                    st_cluster(zs_r + (uint32_t)(1 * DZ + i) * 4u, zn1);
                    st_cluster(zs_r + (uint32_t)(3 * DZ + i) * 4u, zn3);
                    if (cnt > 1) g_Z[((size_t)b1 * TT + t) * DZ + i] = zn1;
                    if (cnt > 3) g_Z[((size_t)b3 * TT + t) * DZ + i] = zn3;
                }
            }
        }
        // barrier B: z chunks exchanged; next step's TF may read zs
        CLUSTER_SYNC_();
    }
}

// ===================== Kernel D: decode out = Z @ obs =====================
__global__ void kdecode(const float* __restrict__ obs, float* __restrict__ out) {
    extern __shared__ float smd[];
    float* obss = smd;               // DZ*64 = 16384 floats (64 KB)
    float* zsm  = obss + DZ * 64;    // 32*DZ =  8192 floats (32 KB)
    int tid = threadIdx.x;           // 512
    for (int idx = tid; idx < DZ * 64; idx += 512) obss[idx] = obs[idx];
    int g = tid & 15, j = tid >> 4;  // 16 x-groups of 4, 32 rows
    int x0 = g * 4;
    for (int it = 0; it < 4; ++it) {
        size_t r0 = (size_t)blockIdx.x * 128 + it * 32;
        __syncthreads();
        for (int idx = tid; idx < 32 * DZ; idx += 512) zsm[idx] = g_Z[r0 * DZ + idx];
        __syncthreads();
        float4 acc = {0, 0, 0, 0};
        const float* zp = zsm + j * DZ;
        #pragma unroll 4
        for (int zi = 0; zi < DZ; ++zi) {
            float zv = zp[zi];
            float4 ov = *(const float4*)&obss[zi * 64 + x0];
            acc.x += zv * ov.x; acc.y += zv * ov.y; acc.z += zv * ov.z; acc.w += zv * ov.w;
        }
        *(float4*)&out[(r0 + j) * 64 + x0] = acc;
    }
}

// ===================== host =====================
extern "C" void kernel_launch(void* const* d_in, const int* in_sizes, int n_in,
                              void* d_out, int out_size) {
    const float* x_gt  = (const float*)d_in[0];   // (256,1024,64)
    const int*   subj  = (const int*)  d_in[1];   // (256,)
    const float* obs   = (const float*)d_in[2];   // (256,64)
    const float* A_t   = (const float*)d_in[3];   // (16,256)
    const float* W1_t  = (const float*)d_in[4];   // (16,256,1024)
    const float* W2_t  = (const float*)d_in[5];   // (16,1024,256)
    const float* h1_t  = (const float*)d_in[6];   // (16,256)
    const float* h2_t  = (const float*)d_in[7];   // (16,1024)
    float* out = (float*)d_out;

    cudaFuncSetAttribute(kdecode, cudaFuncAttributeMaxDynamicSharedMemorySize, 98304);

    kpinv<<<1, 256>>>(obs);
    kforce<<<(BB * TT) / 16, 256>>>(x_gt);
    kgroup<<<1, 256>>>(subj);
    krecur<<<2 * NIT, 1024>>>(A_t, h1_t, h2_t, W1_t, W2_t);   // 76 clusters of 2 CTAs
    kdecode<<<(BB * TT) / 128, 512, 98304>>>(obs, out);
}

// round 15
// speedup vs baseline: 2.8864x; 1.0907x over previous
#include <cuda_runtime.h>
#include <cuda_bf16.h>
#include <cstdint>

// Problem constants (fixed by dataset)
#define BB    256      // batch
#define TT    1024     // timesteps
#define DX    64       // obs dim
#define DZ    256      // latent dim
#define DH    1024     // hidden dim
#define SS    16       // subjects
#define DF    64       // teacher-forced dims
#define ALPHA 0.2f
#define GRP   4        // batches per work item
#define NIT   76       // max work items: sum ceil(n_s/4) <= (256+3*16)/4 = 76

// -------- static device scratch (no allocation allowed) --------
__device__ float g_P64[DX * DF];                    // pinv(obs)[:, :64]  (64x64)
__device__ float g_forcing[(size_t)BB * TT * DF];   // 64 MB
__device__ float g_Z[(size_t)BB * TT * DZ];         // 256 MB latent trajectory
__device__ int   g_order[BB];
__device__ int4  g_work[NIT];                       // (subject, start, cnt, 0)

__device__ __forceinline__ float dot4(float4 a, float4 b) {
    return fmaf(a.x, b.x, fmaf(a.y, b.y, fmaf(a.z, b.z, a.w * b.w)));
}
__device__ __forceinline__ uint32_t smem_u32(const void* p) {
    uint32_t a;
    asm("{ .reg .u64 t; cvta.to.shared.u64 t, %1; cvt.u32.u64 %0, t; }" : "=r"(a) : "l"(p));
    return a;
}
__device__ __forceinline__ uint32_t mapa_u32(uint32_t a, uint32_t r) {
    uint32_t d;
    asm("mapa.shared::cluster.u32 %0, %1, %2;" : "=r"(d) : "r"(a), "r"(r));
    return d;
}
__device__ __forceinline__ void st_cluster4(uint32_t a, float4 v) {
    asm volatile("st.shared::cluster.v4.f32 [%0], {%1,%2,%3,%4};"
                 :: "r"(a), "f"(v.x), "f"(v.y), "f"(v.z), "f"(v.w) : "memory");
}
#define CLUSTER_SYNC_() do { \
    asm volatile("barrier.cluster.arrive.aligned;" ::: "memory"); \
    asm volatile("barrier.cluster.wait.aligned;"   ::: "memory"); \
} while (0)

// ===================== Kernel A: pinv via normal equations =====================
__global__ void kpinv(const float* __restrict__ obs) {
    __shared__ float Gs[64 * 64];
    __shared__ float Au[64 * 64];
    __shared__ float fcol[64];
    __shared__ float s_piv;
    int tid = threadIdx.x;   // 256 threads

    for (int e = tid; e < 4096; e += 256) {
        int a = e >> 6, b = e & 63;
        float s = 0.f;
        for (int r = 0; r < DZ; ++r)
            s += obs[r * DX + a] * obs[r * DX + b];
        Gs[e] = s;
        Au[e] = (a == b) ? 1.f : 0.f;
    }
    __syncthreads();

    for (int c = 0; c < 64; ++c) {
        if (tid == 0) s_piv = 1.f / Gs[c * 64 + c];
        __syncthreads();
        if (tid < 128) {
            if (tid < 64) Gs[c * 64 + tid] *= s_piv;
            else          Au[c * 64 + (tid - 64)] *= s_piv;
        }
        __syncthreads();
        if (tid < 64) fcol[tid] = (tid == c) ? 0.f : Gs[tid * 64 + c];
        __syncthreads();
        for (int idx = tid; idx < 8192; idx += 256) {
            int r = idx >> 7, col = idx & 127;
            float f = fcol[r];
            if (f != 0.f) {
                if (col < 64) Gs[r * 64 + col]        -= f * Gs[c * 64 + col];
                else          Au[r * 64 + (col - 64)] -= f * Au[c * 64 + (col - 64)];
            }
        }
        __syncthreads();
    }

    for (int e = tid; e < 64 * DF; e += 256) {
        int i = e >> 6, j = e & 63;
        float s = 0.f;
        for (int k = 0; k < 64; ++k)
            s += Au[i * 64 + k] * obs[j * DX + k];
        g_P64[i * DF + j] = s;
    }
}

// ===================== Kernel B: forcing[:, :, :64] = x @ P64 =====================
__global__ void kforce(const float* __restrict__ x) {
    __shared__ float Ps[64 * 64];
    __shared__ float xs[4 * 64];
    int tid = threadIdx.x;  // 256
    for (int idx = tid; idx < 4096; idx += 256) Ps[idx] = g_P64[idx];
    int rr = tid >> 6, j = tid & 63;
    for (int it = 0; it < 4; ++it) {
        size_t r0 = (size_t)blockIdx.x * 16 + it * 4;
        __syncthreads();
        xs[tid] = x[r0 * DX + tid];
        __syncthreads();
        float acc = 0.f;
        #pragma unroll
        for (int i = 0; i < 64; ++i)
            acc += xs[rr * 64 + i] * Ps[i * 64 + j];
        g_forcing[(r0 + rr) * DF + j] = acc;
    }
}

// ===================== Kernel C: deterministic subject grouping (GRP=4) =====================
__global__ void kgroup(const int* __restrict__ subject) {
    __shared__ int cnts[SS], base[SS];
    int tid = threadIdx.x;   // 256
    int s = subject[tid];
    if (tid < SS) {
        int c = 0;
        for (int b = 0; b < BB; ++b) c += (subject[b] == tid);
        cnts[tid] = c;
    }
    __syncthreads();
    if (tid == 0) {
        int acc = 0;
        for (int i = 0; i < SS; ++i) { base[i] = acc; acc += cnts[i]; }
    }
    __syncthreads();
    int rank = 0;
    for (int b = 0; b < tid; ++b) rank += (subject[b] == s);
    g_order[base[s] + rank] = tid;
    if (tid == 0) {
        int w = 0;
        for (int s2 = 0; s2 < SS; ++s2) {
            int n = cnts[s2];
            for (int c0 = 0; c0 < n; c0 += GRP) {
                int c = n - c0; if (c > GRP) c = GRP;
                g_work[w] = make_int4(s2, base[s2] + c0, c, 0);
                ++w;
            }
        }
        for (; w < NIT; ++w) g_work[w] = make_int4(0, 0, 0, 0);
    }
}

// ===================== Kernel R: recurrence, cluster-2, GRP=4, cooperative exchange ====
// Rank r owns h in [512r, 512r+512) for phase 1 and i in [128r, 128r+128) for
// phase 2. Halves exchanged via cooperative vectorized DSMEM block copies
// (st.shared::cluster.v4) after each phase; g_Z written with cooperative
// float4 stores staged from smem. All 4 z batches register-cached in phase 1.
__global__ void __launch_bounds__(1024, 1) __cluster_dims__(2, 1, 1)
krecur(const float* __restrict__ A_t,  const float* __restrict__ h1_t,
       const float* __restrict__ h2_t,
       const float* __restrict__ W1_t, const float* __restrict__ W2_t) {
    __shared__ float zs[GRP][DZ];
    __shared__ float hid[GRP][DH];
    __shared__ float As[DZ], h1s[DZ], h2s[DH];
    __shared__ int sb[GRP];

    int item = blockIdx.x >> 1;
    uint32_t rank;
    asm("mov.u32 %0, %%cluster_ctarank;" : "=r"(rank));

    int4 wk = g_work[item];
    int cnt = wk.z;
    if (cnt == 0) return;                 // both CTAs of the cluster exit together
    int s = wk.x;
    int tid = threadIdx.x;                // 1024
    int w = tid >> 5, l = tid & 31;

    if (tid < GRP) sb[tid] = g_order[wk.y + ((tid < cnt) ? tid : cnt - 1)];
    if (tid < DZ) {
        As[tid]  = A_t[s * DZ + tid];
        h1s[tid] = h1_t[s * DZ + tid];
        zs[0][tid] = 0.f; zs[1][tid] = 0.f; zs[2][tid] = 0.f; zs[3][tid] = 0.f;
    }
    h2s[tid] = h2_t[s * DH + tid];
    __syncthreads();

    const float4* w2v = (const float4*)(W2_t + (size_t)s * DH * DZ);  // row h = 64 float4
    const float4* w1v = (const float4*)(W1_t + (size_t)s * DZ * DH);  // row i = 256 float4

    const uint32_t peer  = rank ^ 1u;
    const uint32_t hid_r = mapa_u32(smem_u32(hid), peer);
    const uint32_t zs_r  = mapa_u32(smem_u32(zs),  peer);

    const int hbase = (int)rank * 512;    // phase-1 h range
    const int ibase = (int)rank * 128;    // phase-2 i range

    for (int t = 0; t < TT; ++t) {
        // ---- generalized teacher forcing on first DF dims (both CTAs, identical) ----
        // t==0: z0[:DF]=f0, then a*f0+(1-a)*f0 = f0 -> write f0 directly.
        if (tid < GRP * DF) {
            int j = tid >> 6, d = tid & 63;
            float fv = g_forcing[((size_t)sb[j] * TT + t) * DF + d];
            zs[j][d] = (t == 0) ? fv : (ALPHA * fv + (1.f - ALPHA) * zs[j][d]);
        }
        __syncthreads();

        // cache all 4 z batches in registers for phase 1
        float4 z0a = *(const float4*)&zs[0][4 * l];
        float4 z0b = *(const float4*)&zs[0][128 + 4 * l];
        float4 z1a = *(const float4*)&zs[1][4 * l];
        float4 z1b = *(const float4*)&zs[1][128 + 4 * l];
        float4 z2a = *(const float4*)&zs[2][4 * l];
        float4 z2b = *(const float4*)&zs[2][128 + 4 * l];
        float4 z3a = *(const float4*)&zs[3][4 * l];
        float4 z3b = *(const float4*)&zs[3][128 + 4 * l];

        // ---- phase 1: hid[b][h] = relu( sum_k W2[h][k]*z[b][k] + h2[h] ), own 512 rows ----
        #pragma unroll 2
        for (int p = 0; p < 16; ++p) {
            int h = hbase + p * 32 + w;
            const float4* row = w2v + (size_t)h * 64;
            float4 wa = row[l], wb = row[32 + l];
            float a0 = dot4(wa, z0a) + dot4(wb, z0b);
            float a1 = dot4(wa, z1a) + dot4(wb, z1b);
            float a2 = dot4(wa, z2a) + dot4(wb, z2b);
            float a3 = dot4(wa, z3a) + dot4(wb, z3b);
            // pair reduces: (a0,a1) and (a2,a3); lanes 0 -> (b0,b2), 16 -> (b1,b3)
            float r01 = ((l & 16) ? a1 : a0) + __shfl_xor_sync(0xffffffffu, (l & 16) ? a0 : a1, 16);
            float r23 = ((l & 16) ? a3 : a2) + __shfl_xor_sync(0xffffffffu, (l & 16) ? a2 : a3, 16);
            #pragma unroll
            for (int d = 8; d >= 1; d >>= 1) {
                r01 += __shfl_xor_sync(0xffffffffu, r01, d);
                r23 += __shfl_xor_sync(0xffffffffu, r23, d);
            }
            if (l == 0) {
                hid[0][h] = fmaxf(r01 + h2s[h], 0.f);
                hid[2][h] = fmaxf(r23 + h2s[h], 0.f);
            } else if (l == 16) {
                hid[1][h] = fmaxf(r01 + h2s[h], 0.f);
                hid[3][h] = fmaxf(r23 + h2s[h], 0.f);
            }
        }
        __syncthreads();

        // cooperative hid exchange: own 512-range, all 4 batches -> peer (512 float4)
        if (tid < 512) {
            int b = tid >> 7, off = hbase + (tid & 127) * 4;
            float4 v = *(const float4*)&hid[b][off];
            st_cluster4(hid_r + (uint32_t)(b * DH + off) * 4u, v);
        }
        // barrier A: full hid assembled in both CTAs
        CLUSTER_SYNC_();

        // ---- phase 2: z[b][i] = A[i]*z[b][i] + sum_h W1[i][h]*hid[b][h] + h1[i] ----
        // warp w covers rows i = ibase + w + 32q, q=0..3; hid chunks loaded ONCE per c.
        {
            float acc[4][4];
            #pragma unroll
            for (int q = 0; q < 4; ++q)
                #pragma unroll
                for (int b = 0; b < 4; ++b) acc[q][b] = 0.f;
            #pragma unroll
            for (int c = 0; c < 8; ++c) {
                float4 hc0 = *(const float4*)&hid[0][c * 128 + 4 * l];
                float4 hc1 = *(const float4*)&hid[1][c * 128 + 4 * l];
                float4 hc2 = *(const float4*)&hid[2][c * 128 + 4 * l];
                float4 hc3 = *(const float4*)&hid[3][c * 128 + 4 * l];
                #pragma unroll
                for (int q = 0; q < 4; ++q) {
                    int i = ibase + w + 32 * q;
                    float4 wv = w1v[(size_t)i * 256 + c * 32 + l];
                    acc[q][0] += dot4(wv, hc0);
                    acc[q][1] += dot4(wv, hc1);
                    acc[q][2] += dot4(wv, hc2);
                    acc[q][3] += dot4(wv, hc3);
                }
            }
            #pragma unroll
            for (int q = 0; q < 4; ++q) {
                int i = ibase + w + 32 * q;
                float a0 = acc[q][0], a1 = acc[q][1], a2 = acc[q][2], a3 = acc[q][3];
                float r01 = ((l & 16) ? a1 : a0) + __shfl_xor_sync(0xffffffffu, (l & 16) ? a0 : a1, 16);
                float r23 = ((l & 16) ? a3 : a2) + __shfl_xor_sync(0xffffffffu, (l & 16) ? a2 : a3, 16);
                #pragma unroll
                for (int d = 8; d >= 1; d >>= 1) {
                    r01 += __shfl_xor_sync(0xffffffffu, r01, d);
                    r23 += __shfl_xor_sync(0xffffffffu, r23, d);
                }
                if (l == 0) {
                    zs[0][i] = fmaf(As[i], zs[0][i], r01 + h1s[i]);
                    zs[2][i] = fmaf(As[i], zs[2][i], r23 + h1s[i]);
                } else if (l == 16) {
                    zs[1][i] = fmaf(As[i], zs[1][i], r01 + h1s[i]);
                    zs[3][i] = fmaf(As[i], zs[3][i], r23 + h1s[i]);
                }
            }
        }
        __syncthreads();

        // cooperative g_Z store: own 128-range, all batches (32 float4 per batch)
        if (tid < 128) {
            int b = tid >> 5, off = ibase + (tid & 31) * 4;
            if (b < cnt)
                *(float4*)&g_Z[((size_t)sb[b] * TT + t) * DZ + off] = *(const float4*)&zs[b][off];
        } else if (tid < 256) {
            // cooperative zs exchange: own 128-range, all batches -> peer (32 float4 per batch)
            int u = tid - 128;
            int b = u >> 5, off = ibase + (u & 31) * 4;
            float4 v = *(const float4*)&zs[b][off];
            st_cluster4(zs_r + (uint32_t)(b * DZ + off) * 4u, v);
        }
        // barrier B: z chunks exchanged; next step's TF may read zs
        CLUSTER_SYNC_();
    }
}

// ===================== Kernel D: decode out = Z @ obs =====================
__global__ void kdecode(const float* __restrict__ obs, float* __restrict__ out) {
    extern __shared__ float smd[];
    float* obss = smd;               // DZ*64 = 16384 floats (64 KB)
    float* zsm  = obss + DZ * 64;    // 32*DZ =  8192 floats (32 KB)
    int tid = threadIdx.x;           // 512
    for (int idx = tid; idx < DZ * 64; idx += 512) obss[idx] = obs[idx];
    int g = tid & 15, j = tid >> 4;  // 16 x-groups of 4, 32 rows
    int x0 = g * 4;
    for (int it = 0; it < 4; ++it) {
        size_t r0 = (size_t)blockIdx.x * 128 + it * 32;
        __syncthreads();
        for (int idx = tid; idx < 32 * DZ; idx += 512) zsm[idx] = g_Z[r0 * DZ + idx];
        __syncthreads();
        float4 acc = {0, 0, 0, 0};
        const float* zp = zsm + j * DZ;
        #pragma unroll 4
        for (int zi = 0; zi < DZ; ++zi) {
            float zv = zp[zi];
            float4 ov = *(const float4*)&obss[zi * 64 + x0];
            acc.x += zv * ov.x; acc.y += zv * ov.y; acc.z += zv * ov.z; acc.w += zv * ov.w;
        }
        *(float4*)&out[(r0 + j) * 64 + x0] = acc;
    }
}

// ===================== host =====================
extern "C" void kernel_launch(void* const* d_in, const int* in_sizes, int n_in,
                              void* d_out, int out_size) {
    const float* x_gt  = (const float*)d_in[0];   // (256,1024,64)
    const int*   subj  = (const int*)  d_in[1];   // (256,)
    const float* obs   = (const float*)d_in[2];   // (256,64)
    const float* A_t   = (const float*)d_in[3];   // (16,256)
    const float* W1_t  = (const float*)d_in[4];   // (16,256,1024)
    const float* W2_t  = (const float*)d_in[5];   // (16,1024,256)
    const float* h1_t  = (const float*)d_in[6];   // (16,256)
    const float* h2_t  = (const float*)d_in[7];   // (16,1024)
    float* out = (float*)d_out;

    cudaFuncSetAttribute(kdecode, cudaFuncAttributeMaxDynamicSharedMemorySize, 98304);

    kpinv<<<1, 256>>>(obs);
    kforce<<<(BB * TT) / 16, 256>>>(x_gt);
    kgroup<<<1, 256>>>(subj);
    krecur<<<2 * NIT, 1024>>>(A_t, h1_t, h2_t, W1_t, W2_t);   // 76 clusters of 2 CTAs
    kdecode<<<(BB * TT) / 128, 512, 98304>>>(obs, out);
}